// round 15
// baseline (speedup 1.0000x reference)
#include <cuda_runtime.h>
#include <cuda_bf16.h>

typedef unsigned long long ull;

#define Nn 1024
#define Ff 64
#define Cc 4
#define Ee 32768
#define Hh 256

// ---------------- scratch ----------------
__device__ float4 g_adj[Nn * Nn];            // [i][j] -> 4 channel weights (16 MB)
__device__ float4 g_agg4[Cc * Nn * Ff / 4];  // agg[c][n][f] (1 MB)
__device__ float4 g_P4[Nn * Hh / 4];         // P[i][h] = x_next[i] @ We1[4:68] + be1
__device__ float4 g_Q4[Nn * Hh / 4];         // Q[j][h] = x_next[j] @ We1[68:132]
__device__ int    g_pairflag[Nn * Nn];       // 0/1 per (i,j)
__device__ int    g_pairs[131072];           // compacted list of flagged pairs
__device__ int    g_paircnt;

// ---------------- f32x2 helpers ----------------
__device__ __forceinline__ ull d_pack2(float a, float b) {
    ull r; asm("mov.b64 %0, {%1, %2};" : "=l"(r) : "f"(a), "f"(b)); return r;
}
__device__ __forceinline__ ull f2add(ull a, ull b) {
    ull r; asm("add.rn.f32x2 %0, %1, %2;" : "=l"(r) : "l"(a), "l"(b)); return r;
}
__device__ __forceinline__ ull f2fma(ull a, ull b, ull c) {
    ull r; asm("fma.rn.f32x2 %0, %1, %2, %3;" : "=l"(r) : "l"(a), "l"(b), "l"(c)); return r;
}
// relu on ALU pipe via signed-int max with 0 (IMNMX.S32): exact for non-NaN floats
__device__ __forceinline__ ull f2relu(ull v) {
    int lo, hi;
    asm("mov.b64 {%0, %1}, %2;" : "=r"(lo), "=r"(hi) : "l"(v));
    lo = max(lo, 0); hi = max(hi, 0);
    ull r; asm("mov.b64 %0, {%1, %2};" : "=l"(r) : "r"(lo), "r"(hi));
    return r;
}
__device__ __forceinline__ float f2sum(ull v) {
    float lo, hi;
    asm("mov.b64 {%0, %1}, %2;" : "=f"(lo), "=f"(hi) : "l"(v));
    return lo + hi;
}

// cp.async helpers
__device__ __forceinline__ void cp16(unsigned dst_smem, const void* src) {
    asm volatile("cp.async.cg.shared.global [%0], [%1], 16;"
                 :: "r"(dst_smem), "l"(src));
}
__device__ __forceinline__ void cp_commit() {
    asm volatile("cp.async.commit_group;");
}
template <int N>
__device__ __forceinline__ void cp_wait() {
    asm volatile("cp.async.wait_group %0;" :: "n"(N));
}

// ---------------- K0: zero scratch ----------------
__global__ void zero_kernel() {
    int i = blockIdx.x * 256 + threadIdx.x;   // 1048576 threads
    float4 z = make_float4(0.f, 0.f, 0.f, 0.f);
    g_adj[i] = z;
    g_pairflag[i] = 0;
    if (i < Cc * Nn * Ff / 4) g_agg4[i] = z;
    if (i == 0) g_paircnt = 0;
}

// ---------------- K1: fused edge scatter + adjacency + pair list -------------
// 16 threads per edge (one float4 of F=64 each); q==0 lanes also build the
// dense adjacency and the compacted pair list (warp-aggregated counter).
__global__ void scatter_pair_kernel(const float* __restrict__ x,
                                    const int* __restrict__ ei,
                                    const float* __restrict__ ew) {
    int g = blockIdx.x * 256 + threadIdx.x;   // C*E*16 threads
    int q = g & 15;
    int edge = g >> 4;                        // [0, 131072)
    int c = edge >> 15;
    int e = edge & (Ee - 1);
    int src = ei[c * 2 * Ee + e];
    int tgt = ei[c * 2 * Ee + Ee + e];
    float w = ew[(c << 15) + e];

    // agg scatter (all threads)
    float4 xv = ((const float4*)x)[(src << 4) + q];
    float4* dst = &g_agg4[((c << 10) + tgt) * 16 + q];
    asm volatile("red.global.add.v4.f32 [%0], {%1, %2, %3, %4};"
                 :: "l"(dst), "f"(xv.x * w), "f"(xv.y * w), "f"(xv.z * w), "f"(xv.w * w)
                 : "memory");

    // adjacency + pair list (q==0 lanes only; ballot kept warp-collective)
    int pidx = (src << 10) + tgt;
    bool isnew = false;
    if (q == 0) {
        atomicAdd(&((float*)g_adj)[pidx * 4 + c], w);
        isnew = (atomicExch(&g_pairflag[pidx], 1) == 0);
    }
    unsigned mask = __ballot_sync(0xffffffffu, isnew);
    if (mask) {
        int lane = threadIdx.x & 31;
        int rank = __popc(mask & ((1u << lane) - 1));
        int leader = __ffs(mask) - 1;
        int base = 0;
        if (lane == leader) base = atomicAdd(&g_paircnt, __popc(mask));
        base = __shfl_sync(0xffffffffu, base, leader);
        if (isnew) g_pairs[base + rank] = pidx;
    }
}

// ---------------- K2: node MLP, float4 LDS + cp.async staged weights ---------
#define NM_SMEM_FLOATS (4608 + 3 * 8192)
#define NM_SMEM_BYTES (NM_SMEM_FLOATS * 4)

__global__ void __launch_bounds__(512, 1) node_mlp_kernel(
    const float* __restrict__ x, const float* __restrict__ Wn1,
    const float* __restrict__ bn1, const float* __restrict__ Wn2,
    const float* __restrict__ bn2, const float* __restrict__ We1,
    const float* __restrict__ be1, const float* __restrict__ epsp) {
    extern __shared__ float sm[];
    float* h8  = sm;            // [8][256]
    float* t18 = sm + 2048;     // [8][256]
    float* xn8 = sm + 4096;     // [8][64]
    float* Wtri = sm + 4608;    // 3 x 8192 floats

    const int tid = threadIdx.x;
    const int n0 = blockIdx.x * 8;
    const float oe = 1.0f + *epsp;
    const float* agg = (const float*)g_agg4;
    const unsigned wtri_smem =
        (unsigned)__cvta_generic_to_shared(Wtri);

    for (int idx = tid; idx < 8 * 256; idx += 512) {
        int m = idx >> 8, t = idx & 255;
        int c = t >> 6, f = t & 63;
        int n = n0 + m;
        h8[(m << 8) + t] = agg[((c << 10) + n) * 64 + f] + oe * x[(n << 6) + f];
    }

#pragma unroll
    for (int u = 0; u < 4; u++)
        cp16(wtri_smem + (tid + (u << 9)) * 16, (const float4*)Wn1 + tid + (u << 9));
    cp_commit();
    __syncthreads();   // also covers h8

    // phase 2: t1 = relu(h @ Wn1 + bn1), triple-buffered stages of 32 k
    {
        const int o = tid & 255;
        const int mh = (tid >> 8) << 2;   // 0 or 4
        float acc[4];
#pragma unroll
        for (int m = 0; m < 4; m++) acc[m] = bn1[o];
        for (int s = 0; s < 8; s++) {
            if (s < 7) {
                const float4* src4 = (const float4*)(Wn1 + ((s + 1) << 13));
                unsigned dst = wtri_smem + (((s + 1) % 3) << 15);
#pragma unroll
                for (int u = 0; u < 4; u++)
                    cp16(dst + (tid + (u << 9)) * 16, src4 + tid + (u << 9));
                cp_commit();
                cp_wait<1>();
            } else {
                cp_wait<0>();
            }
            __syncthreads();
            const float* W = Wtri + ((s % 3) << 13);
            const int k0 = s << 5;
#pragma unroll
            for (int g = 0; g < 8; g++) {
                float w0 = W[((g << 2) + 0) * 256 + o];
                float w1 = W[((g << 2) + 1) * 256 + o];
                float w2 = W[((g << 2) + 2) * 256 + o];
                float w3 = W[((g << 2) + 3) * 256 + o];
#pragma unroll
                for (int m = 0; m < 4; m++) {
                    float4 hv = *(const float4*)&h8[((mh + m) << 8) + k0 + (g << 2)];
                    acc[m] = fmaf(hv.x, w0, acc[m]);
                    acc[m] = fmaf(hv.y, w1, acc[m]);
                    acc[m] = fmaf(hv.z, w2, acc[m]);
                    acc[m] = fmaf(hv.w, w3, acc[m]);
                }
            }
        }
#pragma unroll
        for (int m = 0; m < 4; m++) t18[((mh + m) << 8) + o] = fmaxf(acc[m], 0.0f);
    }
    __syncthreads();

    // phase 3: x_next = t1 @ Wn2 + bn2
    {
        const int m = tid >> 6, f = tid & 63;
        float acc = bn2[f];
        for (int c = 0; c < 2; c++) {
            const float4* src4 = (const float4*)(Wn2 + (c << 13));
#pragma unroll
            for (int u = 0; u < 4; u++)
                cp16(wtri_smem + (tid + (u << 9)) * 16, src4 + tid + (u << 9));
            cp_commit();
            cp_wait<0>();
            __syncthreads();
            const int k0 = c << 7;
#pragma unroll
            for (int g = 0; g < 32; g++) {
                float4 tv = *(const float4*)&t18[(m << 8) + k0 + (g << 2)];
                float w0 = Wtri[((g << 2) + 0) * 64 + f];
                float w1 = Wtri[((g << 2) + 1) * 64 + f];
                float w2 = Wtri[((g << 2) + 2) * 64 + f];
                float w3 = Wtri[((g << 2) + 3) * 64 + f];
                acc = fmaf(tv.x, w0, acc);
                acc = fmaf(tv.y, w1, acc);
                acc = fmaf(tv.z, w2, acc);
                acc = fmaf(tv.w, w3, acc);
            }
            __syncthreads();
        }
        xn8[(m << 6) + f] = acc;
    }
    __syncthreads();

    // phase 4: P / Q
    {
        const int o = tid & 255;
        const int mh = (tid >> 8) << 2;   // 0 or 4
        float pacc[4], qacc[4];
#pragma unroll
        for (int m = 0; m < 4; m++) { pacc[m] = be1[o]; qacc[m] = 0.f; }
        float* WA = Wtri;
        float* WB = Wtri + 8192;
        const unsigned wb_smem = wtri_smem + 8192 * 4;
        for (int f0 = 0; f0 < 64; f0 += 32) {
            const float4* srcA = (const float4*)(We1 + (4 + f0) * 256);
            const float4* srcB = (const float4*)(We1 + (68 + f0) * 256);
#pragma unroll
            for (int u = 0; u < 4; u++) {
                cp16(wtri_smem + (tid + (u << 9)) * 16, srcA + tid + (u << 9));
                cp16(wb_smem + (tid + (u << 9)) * 16, srcB + tid + (u << 9));
            }
            cp_commit();
            cp_wait<0>();
            __syncthreads();
#pragma unroll
            for (int g = 0; g < 8; g++) {
                float wa0 = WA[((g << 2) + 0) * 256 + o];
                float wa1 = WA[((g << 2) + 1) * 256 + o];
                float wa2 = WA[((g << 2) + 2) * 256 + o];
                float wa3 = WA[((g << 2) + 3) * 256 + o];
                float wb0 = WB[((g << 2) + 0) * 256 + o];
                float wb1 = WB[((g << 2) + 1) * 256 + o];
                float wb2 = WB[((g << 2) + 2) * 256 + o];
                float wb3 = WB[((g << 2) + 3) * 256 + o];
#pragma unroll
                for (int m = 0; m < 4; m++) {
                    float4 xv = *(const float4*)&xn8[((mh + m) << 6) + f0 + (g << 2)];
                    pacc[m] = fmaf(xv.x, wa0, pacc[m]);
                    pacc[m] = fmaf(xv.y, wa1, pacc[m]);
                    pacc[m] = fmaf(xv.z, wa2, pacc[m]);
                    pacc[m] = fmaf(xv.w, wa3, pacc[m]);
                    qacc[m] = fmaf(xv.x, wb0, qacc[m]);
                    qacc[m] = fmaf(xv.y, wb1, qacc[m]);
                    qacc[m] = fmaf(xv.z, wb2, qacc[m]);
                    qacc[m] = fmaf(xv.w, wb3, qacc[m]);
                }
            }
            __syncthreads();
        }
        float* P = (float*)g_P4;
        float* Q = (float*)g_Q4;
#pragma unroll
        for (int m = 0; m < 4; m++) {
            P[((n0 + mh + m) << 8) + o] = pacc[m];
            Q[((n0 + mh + m) << 8) + o] = qacc[m];
        }
    }
}

// ---------------- K3: dense edge MLP (IMNMX relu, flag-predicated store) -----
#define PS4_STRIDE 65
#define QS4_STRIDE 33
#define DN_SMEM_BYTES ((32 * PS4_STRIDE + 64 * QS4_STRIDE) * 16 + 512 * 8)

__global__ void __launch_bounds__(128, 3) edge_mlp_dense_kernel(
    const float* __restrict__ We2, const float* __restrict__ be2,
    float4* __restrict__ out) {
    extern __shared__ float4 sm4[];
    float4* Ps4 = sm4;                            // [32][65]  (i-row, h-quad)
    float4* Qs4 = sm4 + 32 * PS4_STRIDE;          // [64][33]  (h-quad, j)
    ull* W2P = (ull*)(sm4 + 32 * PS4_STRIDE + 64 * QS4_STRIDE); // [4][128]

    const int tid = threadIdx.x;
    const int lane = tid & 31;
    const int wrp = tid >> 5;
    const int j0 = blockIdx.x << 5;
    const int i0 = blockIdx.y << 5;
    const int ibase = wrp << 3;

    int fl[8];
#pragma unroll
    for (int ii = 0; ii < 8; ii++)
        fl[ii] = g_pairflag[((i0 + ibase + ii) << 10) + j0 + lane];

    for (int idx = tid; idx < 2048; idx += 128) {
        int r = idx >> 6, q = idx & 63;
        Ps4[r * PS4_STRIDE + q] = g_P4[((i0 + r) << 6) + q];
        Qs4[q * QS4_STRIDE + r] = g_Q4[((j0 + r) << 6) + q];   // transpose
    }
    for (int idx = tid; idx < 512; idx += 128) {
        int k = idx >> 7, h2 = idx & 127;
        W2P[(k << 7) + h2] = d_pack2(We2[(h2 << 3) + k], We2[(h2 << 3) + 4 + k]);
    }
    __syncthreads();

    ull acc[8][4];
#pragma unroll
    for (int ii = 0; ii < 8; ii++)
#pragma unroll
        for (int k = 0; k < 4; k++) acc[ii][k] = 0ULL;

#pragma unroll 4
    for (int h2p = 0; h2p < 64; h2p++) {
        float4 qv = Qs4[h2p * QS4_STRIDE + lane];   // conflict-free
        ull q0 = d_pack2(qv.x, qv.y);
        ull q1 = d_pack2(qv.z, qv.w);
        ull w2a[4], w2b[4];
#pragma unroll
        for (int k = 0; k < 4; k++) {
            float4 t = ((const float4*)(W2P + (k << 7)))[h2p];   // broadcast
            w2a[k] = d_pack2(t.x, t.y);
            w2b[k] = d_pack2(t.z, t.w);
        }
#pragma unroll
        for (int ii = 0; ii < 8; ii++) {
            float4 pv = Ps4[(ibase + ii) * PS4_STRIDE + h2p];    // broadcast
            ull v0 = f2relu(f2add(d_pack2(pv.x, pv.y), q0));
            ull v1 = f2relu(f2add(d_pack2(pv.z, pv.w), q1));
#pragma unroll
            for (int k = 0; k < 4; k++) {
                acc[ii][k] = f2fma(v0, w2a[k], acc[ii][k]);
                acc[ii][k] = f2fma(v1, w2b[k], acc[ii][k]);
            }
        }
    }
    const float b0 = be2[0], b1 = be2[1], b2 = be2[2], b3 = be2[3];
#pragma unroll
    for (int ii = 0; ii < 8; ii++) {
        if (!fl[ii]) {
            float4 o;
            o.x = f2sum(acc[ii][0]) + b0;
            o.y = f2sum(acc[ii][1]) + b1;
            o.z = f2sum(acc[ii][2]) + b2;
            o.w = f2sum(acc[ii][3]) + b3;
            out[((i0 + ibase + ii) << 10) + j0 + lane] = o;
        }
    }
}

// ---------------- K4: sparse fix-up (writes all flagged pairs) ---------------
__global__ void __launch_bounds__(256) sparse_fix_kernel(
    const float* __restrict__ We1, const float* __restrict__ We2,
    const float* __restrict__ be2, float4* __restrict__ out) {
    const int lane = threadIdx.x & 31;
    const int wglobal = (blockIdx.x * 256 + threadIdx.x) >> 5;
    const int nwarps = gridDim.x * 8;

    float w1c0[8], w1c1[8], w1c2[8], w1c3[8];
    float4 w2[8];
#pragma unroll
    for (int u = 0; u < 8; u++) {
        int h = lane + (u << 5);
        w1c0[u] = We1[h];
        w1c1[u] = We1[256 + h];
        w1c2[u] = We1[512 + h];
        w1c3[u] = We1[768 + h];
        w2[u] = ((const float4*)We2)[h];
    }
    const float b0 = be2[0], b1 = be2[1], b2 = be2[2], b3 = be2[3];

    const float* P = (const float*)g_P4;
    const float* Q = (const float*)g_Q4;
    const int cnt = g_paircnt;

    for (int w = wglobal; w < cnt; w += nwarps) {
        int p = g_pairs[w];
        int i = p >> 10, j = p & (Nn - 1);
        float4 a = g_adj[p];
        float acc0 = 0.f, acc1 = 0.f, acc2 = 0.f, acc3 = 0.f;
#pragma unroll
        for (int u = 0; u < 8; u++) {
            int h = lane + (u << 5);
            float v = P[(i << 8) + h] + Q[(j << 8) + h];
            v = fmaf(a.x, w1c0[u], v);
            v = fmaf(a.y, w1c1[u], v);
            v = fmaf(a.z, w1c2[u], v);
            v = fmaf(a.w, w1c3[u], v);
            v = fmaxf(v, 0.f);
            acc0 = fmaf(v, w2[u].x, acc0);
            acc1 = fmaf(v, w2[u].y, acc1);
            acc2 = fmaf(v, w2[u].z, acc2);
            acc3 = fmaf(v, w2[u].w, acc3);
        }
#pragma unroll
        for (int off = 16; off; off >>= 1) {
            acc0 += __shfl_xor_sync(0xffffffffu, acc0, off);
            acc1 += __shfl_xor_sync(0xffffffffu, acc1, off);
            acc2 += __shfl_xor_sync(0xffffffffu, acc2, off);
            acc3 += __shfl_xor_sync(0xffffffffu, acc3, off);
        }
        if (lane == 0) {
            float4 o;
            o.x = acc0 + b0;
            o.y = acc1 + b1;
            o.z = acc2 + b2;
            o.w = acc3 + b3;
            out[(i << 10) + j] = o;
        }
    }
}

// ---------------- launch (fused scatter; dense-first fork/join) ----------------
extern "C" void kernel_launch(void* const* d_in, const int* in_sizes, int n_in,
                              void* d_out, int out_size) {
    const float* x   = (const float*)d_in[0];
    const int*   ei  = (const int*)d_in[1];
    const float* ew  = (const float*)d_in[2];
    const float* Wn1 = (const float*)d_in[3];
    const float* bn1 = (const float*)d_in[4];
    const float* Wn2 = (const float*)d_in[5];
    const float* bn2 = (const float*)d_in[6];
    const float* We1 = (const float*)d_in[7];
    const float* be1 = (const float*)d_in[8];
    const float* We2 = (const float*)d_in[9];
    const float* be2 = (const float*)d_in[10];
    const float* eps = (const float*)d_in[11];
    float4* out = (float4*)d_out;

    static cudaStream_t s_aux = nullptr;
    static cudaEvent_t ev_f2 = nullptr, ev_j2 = nullptr;
    if (!s_aux) {
        cudaStreamCreateWithFlags(&s_aux, cudaStreamNonBlocking);
        cudaEventCreateWithFlags(&ev_f2, cudaEventDisableTiming);
        cudaEventCreateWithFlags(&ev_j2, cudaEventDisableTiming);
        cudaFuncSetAttribute(node_mlp_kernel,
                             cudaFuncAttributeMaxDynamicSharedMemorySize, NM_SMEM_BYTES);
        cudaFuncSetAttribute(edge_mlp_dense_kernel,
                             cudaFuncAttributeMaxDynamicSharedMemorySize, DN_SMEM_BYTES);
    }

    zero_kernel<<<(Nn * Nn) / 256, 256>>>();
    scatter_pair_kernel<<<(Cc * Ee * 16) / 256, 256>>>(x, ei, ew);
    node_mlp_kernel<<<Nn / 8, 512, NM_SMEM_BYTES>>>(x, Wn1, bn1, Wn2, bn2, We1, be1, eps);

    // fork: dense launched FIRST (critical path), sparse backfills on s_aux
    cudaEventRecord(ev_f2, 0);
    edge_mlp_dense_kernel<<<dim3(32, 32), 128, DN_SMEM_BYTES>>>(We2, be2, out);
    cudaStreamWaitEvent(s_aux, ev_f2, 0);
    sparse_fix_kernel<<<2048, 256, 0, s_aux>>>(We1, We2, be2, out);

    // final join
    cudaEventRecord(ev_j2, s_aux);
    cudaStreamWaitEvent(0, ev_j2, 0);
}

// round 16
// speedup vs baseline: 1.3915x; 1.3915x over previous
#include <cuda_runtime.h>
#include <cuda_bf16.h>

typedef unsigned long long ull;

#define Nn 1024
#define Ff 64
#define Cc 4
#define Ee 32768
#define Hh 256

// ---------------- scratch ----------------
__device__ float4 g_adj[Nn * Nn];            // [i][j] -> 4 channel weights (16 MB)
__device__ float4 g_agg4[Cc * Nn * Ff / 4];  // agg[c][n][f] (1 MB)
__device__ float4 g_P4[Nn * Hh / 4];         // P[i][h] = x_next[i] @ We1[4:68] + be1
__device__ float4 g_Q4[Nn * Hh / 4];         // Q[j][h] = x_next[j] @ We1[68:132]
__device__ int    g_pairflag[Nn * Nn];       // 0/1 per (i,j)
__device__ int    g_pairs[131072];           // compacted list of flagged pairs
__device__ int    g_paircnt;

// ---------------- f32x2 helpers ----------------
__device__ __forceinline__ ull d_pack2(float a, float b) {
    ull r; asm("mov.b64 %0, {%1, %2};" : "=l"(r) : "f"(a), "f"(b)); return r;
}
__device__ __forceinline__ ull f2add(ull a, ull b) {
    ull r; asm("add.rn.f32x2 %0, %1, %2;" : "=l"(r) : "l"(a), "l"(b)); return r;
}
__device__ __forceinline__ ull f2fma(ull a, ull b, ull c) {
    ull r; asm("fma.rn.f32x2 %0, %1, %2, %3;" : "=l"(r) : "l"(a), "l"(b), "l"(c)); return r;
}
// relu on ALU pipe via signed-int max with 0 (IMNMX.S32): exact for non-NaN floats
__device__ __forceinline__ ull f2relu(ull v) {
    int lo, hi;
    asm("mov.b64 {%0, %1}, %2;" : "=r"(lo), "=r"(hi) : "l"(v));
    lo = max(lo, 0); hi = max(hi, 0);
    ull r; asm("mov.b64 %0, {%1, %2};" : "=l"(r) : "r"(lo), "r"(hi));
    return r;
}
__device__ __forceinline__ float f2sum(ull v) {
    float lo, hi;
    asm("mov.b64 {%0, %1}, %2;" : "=f"(lo), "=f"(hi) : "l"(v));
    return lo + hi;
}

// cp.async helpers
__device__ __forceinline__ void cp16(unsigned dst_smem, const void* src) {
    asm volatile("cp.async.cg.shared.global [%0], [%1], 16;"
                 :: "r"(dst_smem), "l"(src));
}
__device__ __forceinline__ void cp_commit() {
    asm volatile("cp.async.commit_group;");
}
template <int N>
__device__ __forceinline__ void cp_wait() {
    asm volatile("cp.async.wait_group %0;" :: "n"(N));
}

// ---------------- K0: zero scratch ----------------
__global__ void zero_kernel() {
    int i = blockIdx.x * 256 + threadIdx.x;   // 1048576 threads
    float4 z = make_float4(0.f, 0.f, 0.f, 0.f);
    g_adj[i] = z;
    g_pairflag[i] = 0;
    if (i < Cc * Nn * Ff / 4) g_agg4[i] = z;
    if (i == 0) g_paircnt = 0;
}

// ---------------- K1: edge scatter (agg only, v4 reductions) ----------------
__global__ void scatter_kernel(const float* __restrict__ x,
                               const int* __restrict__ ei,
                               const float* __restrict__ ew) {
    int g = blockIdx.x * 256 + threadIdx.x;   // C*E*16 threads
    int q = g & 15;
    int edge = g >> 4;                        // [0, 131072)
    int c = edge >> 15;
    int e = edge & (Ee - 1);
    int src = ei[c * 2 * Ee + e];
    int tgt = ei[c * 2 * Ee + Ee + e];
    float w = ew[(c << 15) + e];
    float4 xv = ((const float4*)x)[(src << 4) + q];
    float4* dst = &g_agg4[((c << 10) + tgt) * 16 + q];
    asm volatile("red.global.add.v4.f32 [%0], {%1, %2, %3, %4};"
                 :: "l"(dst), "f"(xv.x * w), "f"(xv.y * w), "f"(xv.z * w), "f"(xv.w * w)
                 : "memory");
}

// ---------------- K1b: adjacency scatter + warp-aggregated pair list ----------
__global__ void pairlist_kernel(const int* __restrict__ ei,
                                const float* __restrict__ ew) {
    int g = blockIdx.x * 256 + threadIdx.x;   // 131072 threads
    int c = g >> 15;
    int e = g & (Ee - 1);
    int src = ei[c * 2 * Ee + e];
    int tgt = ei[c * 2 * Ee + Ee + e];
    float w = ew[g];
    int pidx = (src << 10) + tgt;
    atomicAdd(&((float*)g_adj)[pidx * 4 + c], w);

    bool isnew = (atomicExch(&g_pairflag[pidx], 1) == 0);
    unsigned mask = __ballot_sync(0xffffffffu, isnew);
    int lane = threadIdx.x & 31;
    int rank = __popc(mask & ((1u << lane) - 1));
    int base = 0;
    int leader = __ffs(mask) - 1;
    if (mask) {
        if (lane == leader) base = atomicAdd(&g_paircnt, __popc(mask));
        base = __shfl_sync(0xffffffffu, base, leader);
        if (isnew) g_pairs[base + rank] = pidx;
    }
}

// ---------------- K2: node MLP, float4 LDS + cp.async staged weights ---------
#define NM_SMEM_FLOATS (4608 + 3 * 8192)
#define NM_SMEM_BYTES (NM_SMEM_FLOATS * 4)

__global__ void __launch_bounds__(512, 1) node_mlp_kernel(
    const float* __restrict__ x, const float* __restrict__ Wn1,
    const float* __restrict__ bn1, const float* __restrict__ Wn2,
    const float* __restrict__ bn2, const float* __restrict__ We1,
    const float* __restrict__ be1, const float* __restrict__ epsp) {
    extern __shared__ float sm[];
    float* h8  = sm;            // [8][256]
    float* t18 = sm + 2048;     // [8][256]
    float* xn8 = sm + 4096;     // [8][64]
    float* Wtri = sm + 4608;    // 3 x 8192 floats

    const int tid = threadIdx.x;
    const int n0 = blockIdx.x * 8;
    const float oe = 1.0f + *epsp;
    const float* agg = (const float*)g_agg4;
    const unsigned wtri_smem =
        (unsigned)__cvta_generic_to_shared(Wtri);

    for (int idx = tid; idx < 8 * 256; idx += 512) {
        int m = idx >> 8, t = idx & 255;
        int c = t >> 6, f = t & 63;
        int n = n0 + m;
        h8[(m << 8) + t] = agg[((c << 10) + n) * 64 + f] + oe * x[(n << 6) + f];
    }

#pragma unroll
    for (int u = 0; u < 4; u++)
        cp16(wtri_smem + (tid + (u << 9)) * 16, (const float4*)Wn1 + tid + (u << 9));
    cp_commit();
    __syncthreads();   // also covers h8

    // phase 2: t1 = relu(h @ Wn1 + bn1), triple-buffered stages of 32 k
    {
        const int o = tid & 255;
        const int mh = (tid >> 8) << 2;   // 0 or 4
        float acc[4];
#pragma unroll
        for (int m = 0; m < 4; m++) acc[m] = bn1[o];
        for (int s = 0; s < 8; s++) {
            if (s < 7) {
                const float4* src4 = (const float4*)(Wn1 + ((s + 1) << 13));
                unsigned dst = wtri_smem + (((s + 1) % 3) << 15);
#pragma unroll
                for (int u = 0; u < 4; u++)
                    cp16(dst + (tid + (u << 9)) * 16, src4 + tid + (u << 9));
                cp_commit();
                cp_wait<1>();
            } else {
                cp_wait<0>();
            }
            __syncthreads();
            const float* W = Wtri + ((s % 3) << 13);
            const int k0 = s << 5;
#pragma unroll
            for (int g = 0; g < 8; g++) {
                float w0 = W[((g << 2) + 0) * 256 + o];
                float w1 = W[((g << 2) + 1) * 256 + o];
                float w2 = W[((g << 2) + 2) * 256 + o];
                float w3 = W[((g << 2) + 3) * 256 + o];
#pragma unroll
                for (int m = 0; m < 4; m++) {
                    float4 hv = *(const float4*)&h8[((mh + m) << 8) + k0 + (g << 2)];
                    acc[m] = fmaf(hv.x, w0, acc[m]);
                    acc[m] = fmaf(hv.y, w1, acc[m]);
                    acc[m] = fmaf(hv.z, w2, acc[m]);
                    acc[m] = fmaf(hv.w, w3, acc[m]);
                }
            }
        }
#pragma unroll
        for (int m = 0; m < 4; m++) t18[((mh + m) << 8) + o] = fmaxf(acc[m], 0.0f);
    }
    __syncthreads();

    // phase 3: x_next = t1 @ Wn2 + bn2
    {
        const int m = tid >> 6, f = tid & 63;
        float acc = bn2[f];
        for (int c = 0; c < 2; c++) {
            const float4* src4 = (const float4*)(Wn2 + (c << 13));
#pragma unroll
            for (int u = 0; u < 4; u++)
                cp16(wtri_smem + (tid + (u << 9)) * 16, src4 + tid + (u << 9));
            cp_commit();
            cp_wait<0>();
            __syncthreads();
            const int k0 = c << 7;
#pragma unroll
            for (int g = 0; g < 32; g++) {
                float4 tv = *(const float4*)&t18[(m << 8) + k0 + (g << 2)];
                float w0 = Wtri[((g << 2) + 0) * 64 + f];
                float w1 = Wtri[((g << 2) + 1) * 64 + f];
                float w2 = Wtri[((g << 2) + 2) * 64 + f];
                float w3 = Wtri[((g << 2) + 3) * 64 + f];
                acc = fmaf(tv.x, w0, acc);
                acc = fmaf(tv.y, w1, acc);
                acc = fmaf(tv.z, w2, acc);
                acc = fmaf(tv.w, w3, acc);
            }
            __syncthreads();
        }
        xn8[(m << 6) + f] = acc;
    }
    __syncthreads();

    // phase 4: P / Q
    {
        const int o = tid & 255;
        const int mh = (tid >> 8) << 2;   // 0 or 4
        float pacc[4], qacc[4];
#pragma unroll
        for (int m = 0; m < 4; m++) { pacc[m] = be1[o]; qacc[m] = 0.f; }
        float* WA = Wtri;
        float* WB = Wtri + 8192;
        const unsigned wb_smem = wtri_smem + 8192 * 4;
        for (int f0 = 0; f0 < 64; f0 += 32) {
            const float4* srcA = (const float4*)(We1 + (4 + f0) * 256);
            const float4* srcB = (const float4*)(We1 + (68 + f0) * 256);
#pragma unroll
            for (int u = 0; u < 4; u++) {
                cp16(wtri_smem + (tid + (u << 9)) * 16, srcA + tid + (u << 9));
                cp16(wb_smem + (tid + (u << 9)) * 16, srcB + tid + (u << 9));
            }
            cp_commit();
            cp_wait<0>();
            __syncthreads();
#pragma unroll
            for (int g = 0; g < 8; g++) {
                float wa0 = WA[((g << 2) + 0) * 256 + o];
                float wa1 = WA[((g << 2) + 1) * 256 + o];
                float wa2 = WA[((g << 2) + 2) * 256 + o];
                float wa3 = WA[((g << 2) + 3) * 256 + o];
                float wb0 = WB[((g << 2) + 0) * 256 + o];
                float wb1 = WB[((g << 2) + 1) * 256 + o];
                float wb2 = WB[((g << 2) + 2) * 256 + o];
                float wb3 = WB[((g << 2) + 3) * 256 + o];
#pragma unroll
                for (int m = 0; m < 4; m++) {
                    float4 xv = *(const float4*)&xn8[((mh + m) << 6) + f0 + (g << 2)];
                    pacc[m] = fmaf(xv.x, wa0, pacc[m]);
                    pacc[m] = fmaf(xv.y, wa1, pacc[m]);
                    pacc[m] = fmaf(xv.z, wa2, pacc[m]);
                    pacc[m] = fmaf(xv.w, wa3, pacc[m]);
                    qacc[m] = fmaf(xv.x, wb0, qacc[m]);
                    qacc[m] = fmaf(xv.y, wb1, qacc[m]);
                    qacc[m] = fmaf(xv.z, wb2, qacc[m]);
                    qacc[m] = fmaf(xv.w, wb3, qacc[m]);
                }
            }
            __syncthreads();
        }
        float* P = (float*)g_P4;
        float* Q = (float*)g_Q4;
#pragma unroll
        for (int m = 0; m < 4; m++) {
            P[((n0 + mh + m) << 8) + o] = pacc[m];
            Q[((n0 + mh + m) << 8) + o] = qacc[m];
        }
    }
}

// ---------------- K3: dense edge MLP (256 thr, 4 rows/warp — measured best) --
// block = 32 i x 32 j tile; 8 warps; warp w owns rows w*4..w*4+3; lane = j_local
#define PQ_STRIDE 260
#define SMEM_BYTES (2 * 32 * PQ_STRIDE * 4 + 512 * 8)

__global__ void __launch_bounds__(256, 3) edge_mlp_dense_kernel(
    const float* __restrict__ We2, const float* __restrict__ be2,
    float4* __restrict__ out) {
    extern __shared__ float smem[];
    float* Ps = smem;                              // [32][260]
    float* Qs = smem + 32 * PQ_STRIDE;             // [32][260]
    ull* W2P = (ull*)(smem + 2 * 32 * PQ_STRIDE);  // [4][128] packed (h, h+1)

    const int tid = threadIdx.x;
    const int lane = tid & 31;
    const int wrp = tid >> 5;
    const int j0 = blockIdx.x << 5;
    const int i0 = blockIdx.y << 5;
    const int ibase = wrp << 2;

    // prefetch pair flags for my 4 output rows (overlaps smem fill)
    int fl[4];
#pragma unroll
    for (int ii = 0; ii < 4; ii++)
        fl[ii] = g_pairflag[((i0 + ibase + ii) << 10) + j0 + lane];

    for (int idx = tid; idx < 32 * 64; idx += 256) {
        int r = idx >> 6, c4 = idx & 63;
        float4 pv = g_P4[((i0 + r) << 6) + c4];
        float4 qv = g_Q4[((j0 + r) << 6) + c4];
        *(float4*)&Ps[r * PQ_STRIDE + (c4 << 2)] = pv;
        *(float4*)&Qs[r * PQ_STRIDE + (c4 << 2)] = qv;
    }
    for (int idx = tid; idx < 512; idx += 256) {
        int k = idx >> 7, h2 = idx & 127;
        W2P[(k << 7) + h2] = d_pack2(We2[(h2 << 3) + k], We2[(h2 << 3) + 4 + k]);
    }
    __syncthreads();

    ull acc[4][4];
#pragma unroll
    for (int ii = 0; ii < 4; ii++)
#pragma unroll
        for (int k = 0; k < 4; k++) acc[ii][k] = 0ULL;

    const float4* Qrow4 = (const float4*)&Qs[lane * PQ_STRIDE];
#pragma unroll 8
    for (int h2p = 0; h2p < 64; h2p++) {
        float4 qv = Qrow4[h2p];
        ull q0 = d_pack2(qv.x, qv.y);
        ull q1 = d_pack2(qv.z, qv.w);
        ull w2a[4], w2b[4];
#pragma unroll
        for (int k = 0; k < 4; k++) {
            float4 t = ((const float4*)(W2P + (k << 7)))[h2p];
            w2a[k] = d_pack2(t.x, t.y);
            w2b[k] = d_pack2(t.z, t.w);
        }
#pragma unroll
        for (int ii = 0; ii < 4; ii++) {
            float4 pv = *(const float4*)&Ps[(ibase + ii) * PQ_STRIDE + (h2p << 2)];
            ull v0 = f2relu(f2add(d_pack2(pv.x, pv.y), q0));
            ull v1 = f2relu(f2add(d_pack2(pv.z, pv.w), q1));
#pragma unroll
            for (int k = 0; k < 4; k++) {
                acc[ii][k] = f2fma(v0, w2a[k], acc[ii][k]);
                acc[ii][k] = f2fma(v1, w2b[k], acc[ii][k]);
            }
        }
    }
    const float b0 = be2[0], b1 = be2[1], b2 = be2[2], b3 = be2[3];
#pragma unroll
    for (int ii = 0; ii < 4; ii++) {
        if (!fl[ii]) {
            float4 o;
            o.x = f2sum(acc[ii][0]) + b0;
            o.y = f2sum(acc[ii][1]) + b1;
            o.z = f2sum(acc[ii][2]) + b2;
            o.w = f2sum(acc[ii][3]) + b3;
            out[((i0 + ibase + ii) << 10) + j0 + lane] = o;
        }
    }
}

// ---------------- K4: sparse fix-up (writes all flagged pairs) ---------------
__global__ void __launch_bounds__(256) sparse_fix_kernel(
    const float* __restrict__ We1, const float* __restrict__ We2,
    const float* __restrict__ be2, float4* __restrict__ out) {
    const int lane = threadIdx.x & 31;
    const int wglobal = (blockIdx.x * 256 + threadIdx.x) >> 5;
    const int nwarps = gridDim.x * 8;

    float w1c0[8], w1c1[8], w1c2[8], w1c3[8];
    float4 w2[8];
#pragma unroll
    for (int u = 0; u < 8; u++) {
        int h = lane + (u << 5);
        w1c0[u] = We1[h];
        w1c1[u] = We1[256 + h];
        w1c2[u] = We1[512 + h];
        w1c3[u] = We1[768 + h];
        w2[u] = ((const float4*)We2)[h];
    }
    const float b0 = be2[0], b1 = be2[1], b2 = be2[2], b3 = be2[3];

    const float* P = (const float*)g_P4;
    const float* Q = (const float*)g_Q4;
    const int cnt = g_paircnt;

    for (int w = wglobal; w < cnt; w += nwarps) {
        int p = g_pairs[w];
        int i = p >> 10, j = p & (Nn - 1);
        float4 a = g_adj[p];
        float acc0 = 0.f, acc1 = 0.f, acc2 = 0.f, acc3 = 0.f;
#pragma unroll
        for (int u = 0; u < 8; u++) {
            int h = lane + (u << 5);
            float v = P[(i << 8) + h] + Q[(j << 8) + h];
            v = fmaf(a.x, w1c0[u], v);
            v = fmaf(a.y, w1c1[u], v);
            v = fmaf(a.z, w1c2[u], v);
            v = fmaf(a.w, w1c3[u], v);
            v = fmaxf(v, 0.f);
            acc0 = fmaf(v, w2[u].x, acc0);
            acc1 = fmaf(v, w2[u].y, acc1);
            acc2 = fmaf(v, w2[u].z, acc2);
            acc3 = fmaf(v, w2[u].w, acc3);
        }
#pragma unroll
        for (int off = 16; off; off >>= 1) {
            acc0 += __shfl_xor_sync(0xffffffffu, acc0, off);
            acc1 += __shfl_xor_sync(0xffffffffu, acc1, off);
            acc2 += __shfl_xor_sync(0xffffffffu, acc2, off);
            acc3 += __shfl_xor_sync(0xffffffffu, acc3, off);
        }
        if (lane == 0) {
            float4 o;
            o.x = acc0 + b0;
            o.y = acc1 + b1;
            o.z = acc2 + b2;
            o.w = acc3 + b3;
            out[(i << 10) + j] = o;
        }
    }
}

// ---------------- launch (R13 structure; measured-best dense) ----------------
extern "C" void kernel_launch(void* const* d_in, const int* in_sizes, int n_in,
                              void* d_out, int out_size) {
    const float* x   = (const float*)d_in[0];
    const int*   ei  = (const int*)d_in[1];
    const float* ew  = (const float*)d_in[2];
    const float* Wn1 = (const float*)d_in[3];
    const float* bn1 = (const float*)d_in[4];
    const float* Wn2 = (const float*)d_in[5];
    const float* bn2 = (const float*)d_in[6];
    const float* We1 = (const float*)d_in[7];
    const float* be1 = (const float*)d_in[8];
    const float* We2 = (const float*)d_in[9];
    const float* be2 = (const float*)d_in[10];
    const float* eps = (const float*)d_in[11];
    float4* out = (float4*)d_out;

    static cudaStream_t s_aux = nullptr;
    static cudaEvent_t ev_f1 = nullptr, ev_j1 = nullptr, ev_f2 = nullptr, ev_j2 = nullptr;
    if (!s_aux) {
        cudaStreamCreateWithFlags(&s_aux, cudaStreamNonBlocking);
        cudaEventCreateWithFlags(&ev_f1, cudaEventDisableTiming);
        cudaEventCreateWithFlags(&ev_j1, cudaEventDisableTiming);
        cudaEventCreateWithFlags(&ev_f2, cudaEventDisableTiming);
        cudaEventCreateWithFlags(&ev_j2, cudaEventDisableTiming);
        cudaFuncSetAttribute(node_mlp_kernel,
                             cudaFuncAttributeMaxDynamicSharedMemorySize, NM_SMEM_BYTES);
        cudaFuncSetAttribute(edge_mlp_dense_kernel,
                             cudaFuncAttributeMaxDynamicSharedMemorySize, SMEM_BYTES);
    }

    zero_kernel<<<(Nn * Nn) / 256, 256>>>();

    // fork: pairlist runs on s_aux concurrently with scatter
    cudaEventRecord(ev_f1, 0);
    cudaStreamWaitEvent(s_aux, ev_f1, 0);
    pairlist_kernel<<<(Cc * Ee) / 256, 256, 0, s_aux>>>(ei, ew);
    scatter_kernel<<<(Cc * Ee * 16) / 256, 256>>>(x, ei, ew);

    // join
    cudaEventRecord(ev_j1, s_aux);
    cudaStreamWaitEvent(0, ev_j1, 0);

    node_mlp_kernel<<<Nn / 8, 512, NM_SMEM_BYTES>>>(x, Wn1, bn1, Wn2, bn2, We1, be1, eps);

    // fork: dense launched FIRST (critical path), sparse backfills on s_aux
    cudaEventRecord(ev_f2, 0);
    edge_mlp_dense_kernel<<<dim3(32, 32), 256, SMEM_BYTES>>>(We2, be2, out);
    cudaStreamWaitEvent(s_aux, ev_f2, 0);
    sparse_fix_kernel<<<2048, 256, 0, s_aux>>>(We1, We2, be2, out);

    // final join
    cudaEventRecord(ev_j2, s_aux);
    cudaStreamWaitEvent(0, ev_j2, 0);
}